// round 13
// baseline (speedup 1.0000x reference)
#include <cuda_runtime.h>
#include <cstdint>

#define C64    64
#define HW     224
#define HP     226
#define NB     8
#define NPIX   (NB * HW * HW)
#define EPS_BN 1e-5f
#define LEAK   0.1f
#define CEILV  255.0f

#define NTILE  1792            /* 8 b * 224 rows; tile = full row, 224px x 64oc */
#define NCTA   148
#define NTHR   448             /* 14 warps: 7 m-pairs x 2 n */

// SMEM float-index layout
#define SM_BIAS 0              /* 64 floats */
#define SM_RED  64             /* 128 floats: sum[64], ssq[64] */
#define SM_B    192            /* 72*512 = 36864 floats, [kstep][wn][gr][gc][ns][2] */
#define SM_A    37056          /* 7 pairs x 3 bufs x 864 floats */
#define ABUFP   864            /* per pair-buffer: 3 rows * 36 px * 8 ch */
#define ABUF4   (ABUFP * 4)    /* bytes */
#define AROWP   288            /* 36 px * 8 floats */
#define SM_FLTS (37056 + 7 * 3 * ABUFP)
#define SMEM_DYN (SM_FLTS * 4) /* 220800 B */

// permutation within each 8-channel group: slot = (c&3)*2 + (c>>2)
#define PERM64(c) (((c) & ~7) | (((c) & 3) << 1) | (((c) >> 2) & 1))

// ---------------- device scratch ----------------
__device__ __align__(16) float  g_xpad[NB * HP * HP * C64];  // padded NHWC, permuted ch
__device__ __align__(16) float  g_wB[72 * 64 * 8];           // frag-major tf32 weights
__device__ double g_sum[C64];
__device__ double g_ssq[C64];
__device__ float  g_scale[C64];
__device__ float  g_shift[C64];

static __device__ __forceinline__ uint32_t tf32_rna(float x) {
    uint32_t u;
    asm("cvt.rna.tf32.f32 %0, %1;" : "=r"(u) : "f"(x));
    return u;
}
static __device__ __forceinline__ uint32_t fu(float x) { return __float_as_uint(x); }

static __device__ __forceinline__ void mma8(float* d, const uint32_t* a,
                                            const uint32_t* b) {
    asm volatile(
        "mma.sync.aligned.m16n8k8.row.col.f32.tf32.tf32.f32 "
        "{%0,%1,%2,%3},{%4,%5,%6,%7},{%8,%9},{%0,%1,%2,%3};"
        : "+f"(d[0]), "+f"(d[1]), "+f"(d[2]), "+f"(d[3])
        : "r"(a[0]), "r"(a[1]), "r"(a[2]), "r"(a[3]), "r"(b[0]), "r"(b[1]));
}
static __device__ __forceinline__ void cp16(uint32_t dst, const void* src) {
    asm volatile("cp.async.cg.shared.global [%0], [%1], 16;"
                 :: "r"(dst), "l"(src));
}
static __device__ __forceinline__ void pair_bar(int id) {
    asm volatile("bar.sync %0, 64;" :: "r"(id) : "memory");
}

// ---------------- kernel: fold 3x3-ternary + 1x1, frag-major tf32 --------
// B layout: [kstep 72][wn 2][gr 8][gc 4][ns 4][2]  (one lane's 4 ns-frags
// are 32 contiguous bytes -> 2x LDS.128 per tap in the conv kernel)
__global__ void fold_k(const float* __restrict__ w1x1,
                       const float* __restrict__ w_bin) {
    int t = blockIdx.x * 256 + threadIdx.x;
    if (t < C64) { g_sum[t] = 0.0; g_ssq[t] = 0.0; }
    if (t >= 64 * 9 * 64) return;
    int o = t & 63;
    int k = (t >> 6) % 9;        // tap
    int i = t / 576;             // in channel
    float s = 0.f;
    #pragma unroll 8
    for (int m = 0; m < 64; ++m)
        s += w1x1[o * 64 + m] * w_bin[(m * 64 + i) * 9 + k];
    int q8 = i >> 3, c8 = i & 7;
    int sl = (c8 & 3) * 2 + (c8 >> 2);       // permuted k-slot 0..7
    int kstep = q8 * 9 + k;
    int idx = kstep * 512 + (o >> 5) * 256 + (o & 7) * 32
            + (sl >> 1) * 8 + ((o >> 3) & 3) * 2 + (sl & 1);
    g_wB[idx] = __uint_as_float(tf32_rna(s));
}

// ---------------- kernel: zero padded border ----------------
__global__ void pad_zero() {
    int p = blockIdx.x;      // 0..899
    int b = blockIdx.y;
    int hp, wp;
    if (p < 226)      { hp = 0;   wp = p; }
    else if (p < 452) { hp = 225; wp = p - 226; }
    else { int q = p - 452; hp = 1 + (q >> 1); wp = (q & 1) * 225; }
    g_xpad[(((size_t)b * HP + hp) * HP + wp) * 64 + threadIdx.x] = 0.f;
}

// ---------------- kernel: NCHW -> padded NHWC, tf32-rounded, permuted ----
__global__ void pad_tr(const float* __restrict__ x) {
    __shared__ float s[64][33];
    int lx = threadIdx.x, ly = threadIdx.y;   // 32, 8
    int w0 = blockIdx.x * 32, h = blockIdx.y, b = blockIdx.z;
    #pragma unroll
    for (int i = 0; i < 8; ++i) {
        int c = i * 8 + ly;
        s[c][lx] = x[(((size_t)b * 64 + c) * HW + h) * HW + w0 + lx];
    }
    __syncthreads();
    float* dst = g_xpad + (((size_t)b * HP + h + 1) * HP + w0 + 1) * 64;
    #pragma unroll
    for (int jj = 0; jj < 8; ++jj) {
        int f = jj * 256 + ly * 32 + lx;
        int ch = f & 63, px = f >> 6;
        dst[(size_t)px * 64 + PERM64(ch)] = __uint_as_float(tf32_rna(s[ch][px]));
    }
}

// ---------------- kernel: pair-decoupled tf32 mma conv + BN stats --------
// Round-12 structure (7 independent 2-warp pair domains, triple-buffered
// cp.async distance-1), plus: B frags via LDS.128 (frag-major layout),
// incremental tile addressing (no div/mod in the hot loop), unrolled
// 8-stage inner loop with hoisted epilogue.
__global__ __launch_bounds__(NTHR, 1)
void conv_mma(const float* __restrict__ bias, float* __restrict__ out) {
    extern __shared__ __align__(16) float sm[];
    float* Bs = sm + SM_B;
    const int tid = threadIdx.x;
    const int lane = tid & 31, wid = tid >> 5;
    const int wn = wid & 1, wm = wid >> 1;       // 7 m-pairs x 2 n-warps
    const int ptid = tid & 63;                    // thread-in-pair
    const int gr = lane >> 2, gc = lane & 3;
    const uint32_t a_smem = (uint32_t)__cvta_generic_to_shared(sm + SM_A);

    // weights + bias -> SMEM once; zero reduction slots
    for (int i = tid; i < 9216; i += NTHR)
        ((float4*)Bs)[i] = ((const float4*)g_wB)[i];
    if (tid < 64) sm[SM_BIAS + tid] = bias[tid];
    if (tid < 128) sm[SM_RED + tid] = 0.f;
    __syncthreads();    // B/bias visible; only CTA-wide bar until the end

    // hoisted per-pair-thread cp.async offsets (204 cp16 per pair-stage)
    uint32_t srcF[4], dstB[4];
    #pragma unroll
    for (int k = 0; k < 4; ++k) {
        int i = ptid + k * 64;
        if (i < 204) {
            int r = i / 68, rem = i % 68;
            int px = rem >> 1, c4 = rem & 1;
            srcF[k] = (uint32_t)((r * HP + wm * 32 + px) * 64 + c4 * 4);
            dstB[k] = (uint32_t)((wm * (3 * ABUFP) + r * AROWP + px * 8
                                  + c4 * 4) * 4);
        }
    }
    const int ncp = (ptid < 12) ? 4 : 3;

    const float* Apair = sm + SM_A + wm * (3 * ABUFP);
    const int afrag = gr * 8 + gc * 2;                 // within pair buffer
    const int bfrag = wn * 256 + gr * 32 + gc * 8;     // frag-major B

    const int ntiles = (NTILE - blockIdx.x + NCTA - 1) / NCTA;

    auto issue = [&](const float* xrow, uint32_t boff) {
        #pragma unroll
        for (int k = 0; k < 4; ++k)
            if (k < ncp) cp16(a_smem + boff + dstB[k], xrow + srcF[k]);
        asm volatile("cp.async.commit_group;");
    };

    float ps[4][2], qs[4][2];   // per-thread BN partials
    #pragma unroll
    for (int ns = 0; ns < 4; ++ns)
        ps[ns][0] = ps[ns][1] = qs[ns][0] = qs[ns][1] = 0.f;

    // incremental tile coords (bid < 148 < 224 -> h=bid, b=0)
    int b = 0, h = blockIdx.x;
    const float* xcur = g_xpad + ((size_t)h * HP) * 64;

    issue(xcur, 0);             // stage 0, buffer 0
    int nb = 1;                 // buffer index of stage g+1 (mod 3)

    for (int j = 0; j < ntiles; ++j) {
        const bool lastj = (j == ntiles - 1);
        int hn = h + NCTA, bn = b;
        if (hn >= 224) { hn -= 224; bn += 1; }
        const float* xnxt = g_xpad + (((size_t)bn * HP + hn) * HP) * 64;

        float acc[2][4][4];
        #pragma unroll
        for (int ms = 0; ms < 2; ++ms)
            #pragma unroll
            for (int ns = 0; ns < 4; ++ns)
                #pragma unroll
                for (int q2 = 0; q2 < 4; ++q2) acc[ms][ns][q2] = 0.f;

        #pragma unroll
        for (int q8 = 0; q8 < 8; ++q8) {
            // issue stage g+1, then wait for stage g
            if (q8 < 7) {
                issue(xcur + (q8 + 1) * 8, (uint32_t)nb * ABUF4);
                asm volatile("cp.async.wait_group 1;");
            } else if (!lastj) {
                issue(xnxt, (uint32_t)nb * ABUF4);
                asm volatile("cp.async.wait_group 1;");
            } else {
                asm volatile("cp.async.wait_group 0;");
            }
            nb = (nb == 2) ? 0 : nb + 1;
            pair_bar(wm + 1);          // copy g visible to both pair warps

            // cb = buffer of stage g  (== nb+1 mod 3 after increment)
            const int cb = (nb == 2) ? 0 : nb + 1;
            const float* Ab = Apair + cb * ABUFP + afrag;
            const float* Bq = Bs + q8 * 4608 + bfrag;
            #pragma unroll
            for (int kh = 0; kh < 3; ++kh) {
                #pragma unroll
                for (int kw = 0; kw < 3; ++kw) {
                    uint32_t A[2][4];
                    #pragma unroll
                    for (int ms = 0; ms < 2; ++ms) {
                        const float* ap = Ab + kh * AROWP
                            + (ms * 16 + kw) * 8;
                        float2 u = *(const float2*)ap;
                        float2 v = *(const float2*)(ap + 64);
                        A[ms][0] = fu(u.x); A[ms][1] = fu(v.x);
                        A[ms][2] = fu(u.y); A[ms][3] = fu(v.y);
                    }
                    const float* bp = Bq + (kh * 3 + kw) * 512;
                    float4 b01 = *(const float4*)bp;
                    float4 b23 = *(const float4*)(bp + 4);
                    uint32_t B0[2] = { fu(b01.x), fu(b01.y) };
                    uint32_t B1[2] = { fu(b01.z), fu(b01.w) };
                    uint32_t B2[2] = { fu(b23.x), fu(b23.y) };
                    uint32_t B3[2] = { fu(b23.z), fu(b23.w) };
                    mma8(acc[0][0], A[0], B0);
                    mma8(acc[1][0], A[1], B0);
                    mma8(acc[0][1], A[0], B1);
                    mma8(acc[1][1], A[1], B1);
                    mma8(acc[0][2], A[0], B2);
                    mma8(acc[1][2], A[1], B2);
                    mma8(acc[0][3], A[0], B3);
                    mma8(acc[1][3], A[1], B3);
                }
            }
        }

        // epilogue: + bias, NCHW store, BN partials
        {
            const size_t chstr = (size_t)HW * HW;
            const int pxb = wm * 32 + gr;
            const int ob  = wn * 32 + gc * 2;
            float* obase = out + ((size_t)b * 64) * chstr + (size_t)h * HW;
            #pragma unroll
            for (int ms = 0; ms < 2; ++ms) {
                #pragma unroll
                for (int ns = 0; ns < 4; ++ns) {
                    int o0 = ob + ns * 8;
                    float b0 = sm[SM_BIAS + o0], b1 = sm[SM_BIAS + o0 + 1];
                    float y0 = acc[ms][ns][0] + b0;
                    float y1 = acc[ms][ns][1] + b1;
                    float y2 = acc[ms][ns][2] + b0;
                    float y3 = acc[ms][ns][3] + b1;
                    float* p = obase + (size_t)o0 * chstr + pxb + ms * 16;
                    p[0]         = y0;
                    p[chstr]     = y1;
                    p[8]         = y2;
                    p[chstr + 8] = y3;
                    ps[ns][0] += y0 + y2;  qs[ns][0] += y0 * y0 + y2 * y2;
                    ps[ns][1] += y1 + y3;  qs[ns][1] += y1 * y1 + y3 * y3;
                }
            }
        }
        b = bn; h = hn; xcur = xnxt;
    }

    // BN partial reduction: regs -> shared -> global doubles
    #pragma unroll
    for (int ns = 0; ns < 4; ++ns) {
        int o0 = wn * 32 + ns * 8 + gc * 2;
        atomicAdd(&sm[SM_RED + o0],          ps[ns][0]);
        atomicAdd(&sm[SM_RED + o0 + 1],      ps[ns][1]);
        atomicAdd(&sm[SM_RED + 64 + o0],     qs[ns][0]);
        atomicAdd(&sm[SM_RED + 64 + o0 + 1], qs[ns][1]);
    }
    __syncthreads();
    if (tid < 64) {
        atomicAdd(&g_sum[tid], (double)sm[SM_RED + tid]);
        atomicAdd(&g_ssq[tid], (double)sm[SM_RED + 64 + tid]);
    }
}

// ---------------- kernel: finalize BN ----------------
__global__ void stats_k(const float* __restrict__ gamma,
                        const float* __restrict__ beta) {
    int c = threadIdx.x;
    if (c >= C64) return;
    double m = g_sum[c] / (double)NPIX;
    double v = g_ssq[c] / (double)NPIX - m * m;
    float a = gamma[c] * rsqrtf((float)v + EPS_BN);
    g_scale[c] = a;
    g_shift[c] = beta[c] - (float)m * a;
}

// ---------------- kernel: normalize + leaky relu + clamp ----------------
__global__ void act_k(float* __restrict__ out) {
    int idx = blockIdx.x * blockDim.x + threadIdx.x;
    const int total4 = NB * C64 * HW * HW / 4;
    if (idx >= total4) return;
    int plane = (idx * 4) / (HW * HW);
    int c = plane & 63;
    float a = g_scale[c], sh = g_shift[c];
    float4 v = ((float4*)out)[idx];
    float* vp = &v.x;
    #pragma unroll
    for (int p = 0; p < 4; ++p) {
        float y = a * vp[p] + sh;
        y = (y >= 0.f) ? y : LEAK * y;
        y = fminf(fmaxf(y, 0.f), CEILV);
        vp[p] = y;
    }
    ((float4*)out)[idx] = v;
}

// ---------------- launch ----------------
extern "C" void kernel_launch(void* const* d_in, const int* in_sizes, int n_in,
                              void* d_out, int out_size) {
    const float* x     = (const float*)d_in[0];
    const float* w_bin = (const float*)d_in[1];
    const float* w1x1  = (const float*)d_in[2];
    const float* b1x1  = (const float*)d_in[3];
    const float* gamma = (const float*)d_in[4];
    const float* beta  = (const float*)d_in[5];
    float* out = (float*)d_out;

    cudaFuncSetAttribute(conv_mma, cudaFuncAttributeMaxDynamicSharedMemorySize,
                         SMEM_DYN);

    fold_k<<<(64 * 9 * 64 + 255) / 256, 256>>>(w1x1, w_bin);
    pad_zero<<<dim3(900, NB), 64>>>();
    pad_tr<<<dim3(7, HW, NB), dim3(32, 8)>>>(x);
    conv_mma<<<NCTA, NTHR, SMEM_DYN>>>(b1x1, out);
    stats_k<<<1, 64>>>(gamma, beta);
    int total4 = NB * C64 * HW * HW / 4;
    act_k<<<(total4 + 255) / 256, 256>>>(out);
}

// round 14
// speedup vs baseline: 1.0123x; 1.0123x over previous
#include <cuda_runtime.h>
#include <cstdint>

#define C64    64
#define HW     224
#define HP     226
#define NB     8
#define NPIX   (NB * HW * HW)
#define EPS_BN 1e-5f
#define LEAK   0.1f
#define CEILV  255.0f

#define NTILE  1792            /* 8 b * 224 rows; tile = full row, 224px x 64oc */
#define NCTA   148
#define NTHR   448             /* 14 warps: 7 m-pairs x 2 n */

// SMEM float-index layout
#define SM_BIAS 0              /* 64 floats */
#define SM_RED  64             /* 128 floats: sum[64], ssq[64] */
#define SM_B    192            /* 72*512 floats, frag-major + XOR16 swizzle */
#define SM_A    37056          /* 7 pairs x 3 bufs x 864 floats */
#define ABUFP   864            /* per pair-buffer: 3 rows * 36 px * 8 ch */
#define ABUF4   (ABUFP * 4)    /* bytes */
#define AROWP   288            /* 36 px * 8 floats */
#define SM_FLTS (37056 + 7 * 3 * ABUFP)
#define SMEM_DYN (SM_FLTS * 4) /* 220800 B */

// permutation within each 8-channel group: slot = (c&3)*2 + (c>>2)
#define PERM64(c) (((c) & ~7) | (((c) & 3) << 1) | (((c) >> 2) & 1))

// ---------------- device scratch ----------------
__device__ __align__(16) float  g_xpad[NB * HP * HP * C64];  // padded NHWC, permuted ch
__device__ __align__(16) float  g_wB[72 * 64 * 8];           // frag-major tf32 weights
__device__ double g_sum[C64];
__device__ double g_ssq[C64];
__device__ float  g_scale[C64];
__device__ float  g_shift[C64];

static __device__ __forceinline__ uint32_t tf32_rna(float x) {
    uint32_t u;
    asm("cvt.rna.tf32.f32 %0, %1;" : "=r"(u) : "f"(x));
    return u;
}
static __device__ __forceinline__ uint32_t fu(float x) { return __float_as_uint(x); }

static __device__ __forceinline__ void mma8(float* d, const uint32_t* a,
                                            const uint32_t* b) {
    asm volatile(
        "mma.sync.aligned.m16n8k8.row.col.f32.tf32.tf32.f32 "
        "{%0,%1,%2,%3},{%4,%5,%6,%7},{%8,%9},{%0,%1,%2,%3};"
        : "+f"(d[0]), "+f"(d[1]), "+f"(d[2]), "+f"(d[3])
        : "r"(a[0]), "r"(a[1]), "r"(a[2]), "r"(a[3]), "r"(b[0]), "r"(b[1]));
}
static __device__ __forceinline__ void cp16(uint32_t dst, const void* src) {
    asm volatile("cp.async.cg.shared.global [%0], [%1], 16;"
                 :: "r"(dst), "l"(src));
}
static __device__ __forceinline__ void pair_bar(int id) {
    asm volatile("bar.sync %0, 64;" :: "r"(id) : "memory");
}

// ---------------- kernel: fold 3x3-ternary + 1x1, frag-major tf32 --------
// B layout per kstep (512 floats): [wn 2][gr 8][16B-unit 4][4 floats],
// physical unit = (gc*2 + (ns>>1)) ^ (gr&1)  -> conflict-free LDS.128.
__global__ void fold_k(const float* __restrict__ w1x1,
                       const float* __restrict__ w_bin) {
    int t = blockIdx.x * 256 + threadIdx.x;
    if (t < C64) { g_sum[t] = 0.0; g_ssq[t] = 0.0; }
    if (t >= 64 * 9 * 64) return;
    int o = t & 63;
    int k = (t >> 6) % 9;        // tap
    int i = t / 576;             // in channel
    float s = 0.f;
    #pragma unroll 8
    for (int m = 0; m < 64; ++m)
        s += w1x1[o * 64 + m] * w_bin[(m * 64 + i) * 9 + k];
    int q8 = i >> 3, c8 = i & 7;
    int sl = (c8 & 3) * 2 + (c8 >> 2);       // permuted k-slot 0..7
    int kstep = q8 * 9 + k;
    int gr_ = o & 7;
    int ns_ = (o >> 3) & 3;
    int gcl = sl >> 1, reg = sl & 1;
    int unit = (gcl * 2 + (ns_ >> 1)) ^ (gr_ & 1);
    int idx = kstep * 512 + (o >> 5) * 256 + gr_ * 32
            + unit * 4 + (ns_ & 1) * 2 + reg;
    g_wB[idx] = __uint_as_float(tf32_rna(s));
}

// ---------------- kernel: zero padded border ----------------
__global__ void pad_zero() {
    int p = blockIdx.x;      // 0..899
    int b = blockIdx.y;
    int hp, wp;
    if (p < 226)      { hp = 0;   wp = p; }
    else if (p < 452) { hp = 225; wp = p - 226; }
    else { int q = p - 452; hp = 1 + (q >> 1); wp = (q & 1) * 225; }
    g_xpad[(((size_t)b * HP + hp) * HP + wp) * 64 + threadIdx.x] = 0.f;
}

// ---------------- kernel: NCHW -> padded NHWC, tf32-rounded, permuted ----
__global__ void pad_tr(const float* __restrict__ x) {
    __shared__ float s[64][33];
    int lx = threadIdx.x, ly = threadIdx.y;   // 32, 8
    int w0 = blockIdx.x * 32, h = blockIdx.y, b = blockIdx.z;
    #pragma unroll
    for (int i = 0; i < 8; ++i) {
        int c = i * 8 + ly;
        s[c][lx] = x[(((size_t)b * 64 + c) * HW + h) * HW + w0 + lx];
    }
    __syncthreads();
    float* dst = g_xpad + (((size_t)b * HP + h + 1) * HP + w0 + 1) * 64;
    #pragma unroll
    for (int jj = 0; jj < 8; ++jj) {
        int f = jj * 256 + ly * 32 + lx;
        int ch = f & 63, px = f >> 6;
        dst[(size_t)px * 64 + PERM64(ch)] = __uint_as_float(tf32_rna(s[ch][px]));
    }
}

// ---------------- kernel: pair-decoupled tf32 mma conv + BN stats --------
// Round-12 structure (7 independent 2-warp pair domains, triple-buffered
// cp.async distance-1) + round-13 incremental addressing + swizzled
// conflict-free LDS.128 B fragments.
__global__ __launch_bounds__(NTHR, 1)
void conv_mma(const float* __restrict__ bias, float* __restrict__ out) {
    extern __shared__ __align__(16) float sm[];
    float* Bs = sm + SM_B;
    const int tid = threadIdx.x;
    const int lane = tid & 31, wid = tid >> 5;
    const int wn = wid & 1, wm = wid >> 1;       // 7 m-pairs x 2 n-warps
    const int ptid = tid & 63;                    // thread-in-pair
    const int gr = lane >> 2, gc = lane & 3;
    const uint32_t a_smem = (uint32_t)__cvta_generic_to_shared(sm + SM_A);

    // weights + bias -> SMEM once; zero reduction slots
    for (int i = tid; i < 9216; i += NTHR)
        ((float4*)Bs)[i] = ((const float4*)g_wB)[i];
    if (tid < 64) sm[SM_BIAS + tid] = bias[tid];
    if (tid < 128) sm[SM_RED + tid] = 0.f;
    __syncthreads();    // B/bias visible; only CTA-wide bar until the end

    // hoisted per-pair-thread cp.async offsets (204 cp16 per pair-stage)
    uint32_t srcF[4], dstB[4];
    #pragma unroll
    for (int k = 0; k < 4; ++k) {
        int i = ptid + k * 64;
        if (i < 204) {
            int r = i / 68, rem = i % 68;
            int px = rem >> 1, c4 = rem & 1;
            srcF[k] = (uint32_t)((r * HP + wm * 32 + px) * 64 + c4 * 4);
            dstB[k] = (uint32_t)((wm * (3 * ABUFP) + r * AROWP + px * 8
                                  + c4 * 4) * 4);
        }
    }
    const int ncp = (ptid < 12) ? 4 : 3;

    const float* Apair = sm + SM_A + wm * (3 * ABUFP);
    const int afrag = gr * 8 + gc * 2;                 // within pair buffer
    const int bfrag = wn * 256 + gr * 32 + gc * 8;     // frag-major B
    const uintptr_t bsw = (uintptr_t)((gr & 1) * 16);  // XOR16 swizzle

    const int ntiles = (NTILE - blockIdx.x + NCTA - 1) / NCTA;

    auto issue = [&](const float* xrow, uint32_t boff) {
        #pragma unroll
        for (int k = 0; k < 4; ++k)
            if (k < ncp) cp16(a_smem + boff + dstB[k], xrow + srcF[k]);
        asm volatile("cp.async.commit_group;");
    };

    float ps[4][2], qs[4][2];   // per-thread BN partials
    #pragma unroll
    for (int ns = 0; ns < 4; ++ns)
        ps[ns][0] = ps[ns][1] = qs[ns][0] = qs[ns][1] = 0.f;

    // incremental tile coords (bid < 148 < 224 -> h=bid, b=0)
    int b = 0, h = blockIdx.x;
    const float* xcur = g_xpad + ((size_t)h * HP) * 64;

    issue(xcur, 0);             // stage 0, buffer 0
    int nb = 1;                 // buffer index of stage g+1 (mod 3)

    for (int j = 0; j < ntiles; ++j) {
        const bool lastj = (j == ntiles - 1);
        int hn = h + NCTA, bn = b;
        if (hn >= 224) { hn -= 224; bn += 1; }
        const float* xnxt = g_xpad + (((size_t)bn * HP + hn) * HP) * 64;

        float acc[2][4][4];
        #pragma unroll
        for (int ms = 0; ms < 2; ++ms)
            #pragma unroll
            for (int ns = 0; ns < 4; ++ns)
                #pragma unroll
                for (int q2 = 0; q2 < 4; ++q2) acc[ms][ns][q2] = 0.f;

        #pragma unroll
        for (int q8 = 0; q8 < 8; ++q8) {
            // issue stage g+1, then wait for stage g
            if (q8 < 7) {
                issue(xcur + (q8 + 1) * 8, (uint32_t)nb * ABUF4);
                asm volatile("cp.async.wait_group 1;");
            } else if (!lastj) {
                issue(xnxt, (uint32_t)nb * ABUF4);
                asm volatile("cp.async.wait_group 1;");
            } else {
                asm volatile("cp.async.wait_group 0;");
            }
            nb = (nb == 2) ? 0 : nb + 1;
            pair_bar(wm + 1);          // copy g visible to both pair warps

            // cb = buffer of stage g  (== nb+1 mod 3 after increment)
            const int cb = (nb == 2) ? 0 : nb + 1;
            const float* Ab = Apair + cb * ABUFP + afrag;
            const float* Bq = Bs + q8 * 512 * 9 + bfrag;
            #pragma unroll
            for (int kh = 0; kh < 3; ++kh) {
                #pragma unroll
                for (int kw = 0; kw < 3; ++kw) {
                    uint32_t A[2][4];
                    #pragma unroll
                    for (int ms = 0; ms < 2; ++ms) {
                        const float* ap = Ab + kh * AROWP
                            + (ms * 16 + kw) * 8;
                        float2 u = *(const float2*)ap;
                        float2 v = *(const float2*)(ap + 64);
                        A[ms][0] = fu(u.x); A[ms][1] = fu(v.x);
                        A[ms][2] = fu(u.y); A[ms][3] = fu(v.y);
                    }
                    const uintptr_t bp =
                        (uintptr_t)(Bq + (kh * 3 + kw) * 512);
                    float4 b01 = *(const float4*)(bp ^ bsw);
                    float4 b23 = *(const float4*)((bp + 16) ^ bsw);
                    uint32_t B0[2] = { fu(b01.x), fu(b01.y) };
                    uint32_t B1[2] = { fu(b01.z), fu(b01.w) };
                    uint32_t B2[2] = { fu(b23.x), fu(b23.y) };
                    uint32_t B3[2] = { fu(b23.z), fu(b23.w) };
                    mma8(acc[0][0], A[0], B0);
                    mma8(acc[1][0], A[1], B0);
                    mma8(acc[0][1], A[0], B1);
                    mma8(acc[1][1], A[1], B1);
                    mma8(acc[0][2], A[0], B2);
                    mma8(acc[1][2], A[1], B2);
                    mma8(acc[0][3], A[0], B3);
                    mma8(acc[1][3], A[1], B3);
                }
            }
        }

        // epilogue: + bias, NCHW store, BN partials
        {
            const size_t chstr = (size_t)HW * HW;
            const int pxb = wm * 32 + gr;
            const int ob  = wn * 32 + gc * 2;
            float* obase = out + ((size_t)b * 64) * chstr + (size_t)h * HW;
            #pragma unroll
            for (int ms = 0; ms < 2; ++ms) {
                #pragma unroll
                for (int ns = 0; ns < 4; ++ns) {
                    int o0 = ob + ns * 8;
                    float b0 = sm[SM_BIAS + o0], b1 = sm[SM_BIAS + o0 + 1];
                    float y0 = acc[ms][ns][0] + b0;
                    float y1 = acc[ms][ns][1] + b1;
                    float y2 = acc[ms][ns][2] + b0;
                    float y3 = acc[ms][ns][3] + b1;
                    float* p = obase + (size_t)o0 * chstr + pxb + ms * 16;
                    p[0]         = y0;
                    p[chstr]     = y1;
                    p[8]         = y2;
                    p[chstr + 8] = y3;
                    ps[ns][0] += y0 + y2;  qs[ns][0] += y0 * y0 + y2 * y2;
                    ps[ns][1] += y1 + y3;  qs[ns][1] += y1 * y1 + y3 * y3;
                }
            }
        }
        b = bn; h = hn; xcur = xnxt;
    }

    // BN partial reduction: regs -> shared -> global doubles
    #pragma unroll
    for (int ns = 0; ns < 4; ++ns) {
        int o0 = wn * 32 + ns * 8 + gc * 2;
        atomicAdd(&sm[SM_RED + o0],          ps[ns][0]);
        atomicAdd(&sm[SM_RED + o0 + 1],      ps[ns][1]);
        atomicAdd(&sm[SM_RED + 64 + o0],     qs[ns][0]);
        atomicAdd(&sm[SM_RED + 64 + o0 + 1], qs[ns][1]);
    }
    __syncthreads();
    if (tid < 64) {
        atomicAdd(&g_sum[tid], (double)sm[SM_RED + tid]);
        atomicAdd(&g_ssq[tid], (double)sm[SM_RED + 64 + tid]);
    }
}

// ---------------- kernel: finalize BN ----------------
__global__ void stats_k(const float* __restrict__ gamma,
                        const float* __restrict__ beta) {
    int c = threadIdx.x;
    if (c >= C64) return;
    double m = g_sum[c] / (double)NPIX;
    double v = g_ssq[c] / (double)NPIX - m * m;
    float a = gamma[c] * rsqrtf((float)v + EPS_BN);
    g_scale[c] = a;
    g_shift[c] = beta[c] - (float)m * a;
}

// ---------------- kernel: normalize + leaky relu + clamp ----------------
__global__ void act_k(float* __restrict__ out) {
    int idx = blockIdx.x * blockDim.x + threadIdx.x;
    const int total4 = NB * C64 * HW * HW / 4;
    if (idx >= total4) return;
    int plane = (idx * 4) / (HW * HW);
    int c = plane & 63;
    float a = g_scale[c], sh = g_shift[c];
    float4 v = ((float4*)out)[idx];
    float* vp = &v.x;
    #pragma unroll
    for (int p = 0; p < 4; ++p) {
        float y = a * vp[p] + sh;
        y = (y >= 0.f) ? y : LEAK * y;
        y = fminf(fmaxf(y, 0.f), CEILV);
        vp[p] = y;
    }
    ((float4*)out)[idx] = v;
}

// ---------------- launch ----------------
extern "C" void kernel_launch(void* const* d_in, const int* in_sizes, int n_in,
                              void* d_out, int out_size) {
    const float* x     = (const float*)d_in[0];
    const float* w_bin = (const float*)d_in[1];
    const float* w1x1  = (const float*)d_in[2];
    const float* b1x1  = (const float*)d_in[3];
    const float* gamma = (const float*)d_in[4];
    const float* beta  = (const float*)d_in[5];
    float* out = (float*)d_out;

    cudaFuncSetAttribute(conv_mma, cudaFuncAttributeMaxDynamicSharedMemorySize,
                         SMEM_DYN);

    fold_k<<<(64 * 9 * 64 + 255) / 256, 256>>>(w1x1, w_bin);
    pad_zero<<<dim3(900, NB), 64>>>();
    pad_tr<<<dim3(7, HW, NB), dim3(32, 8)>>>(x);
    conv_mma<<<NCTA, NTHR, SMEM_DYN>>>(b1x1, out);
    stats_k<<<1, 64>>>(gamma, beta);
    int total4 = NB * C64 * HW * HW / 4;
    act_k<<<(total4 + 255) / 256, 256>>>(out);
}

// round 15
// speedup vs baseline: 1.0279x; 1.0154x over previous
#include <cuda_runtime.h>
#include <cstdint>

#define C64    64
#define HW     224
#define HP     226
#define NB     8
#define NPIX   (NB * HW * HW)
#define EPS_BN 1e-5f
#define LEAK   0.1f
#define CEILV  255.0f

#define NTILE  1792            /* 8 b * 224 rows; tile = full row, 224px x 64oc */
#define NCTA   148
#define NTHR   448             /* 14 warps: 7 m-pairs x 2 n */

// SMEM float-index layout
#define SM_BIAS 0              /* 64 floats */
#define SM_RED  64             /* 128 floats: sum[64], ssq[64] */
#define SM_B    192            /* 72*64*8 = 36864 floats, [kstep][o][slot8] */
#define SM_A    37056          /* 7 pairs x 3 bufs x 864 floats */
#define ABUFP   864            /* per pair-buffer: 3 rows * 36 px * 8 ch */
#define ABUF4   3456           /* bytes per pair-buffer */
#define AROWP   288            /* 36 px * 8 floats */
#define SM_FLTS (37056 + 7 * 3 * ABUFP)
#define SMEM_DYN (SM_FLTS * 4) /* 220800 B */

// permutation within each 8-channel group: slot = (c&3)*2 + (c>>2)
#define PERM64(c) (((c) & ~7) | (((c) & 3) << 1) | (((c) >> 2) & 1))

// ---------------- device scratch ----------------
__device__ __align__(16) float  g_xpad[NB * HP * HP * C64];  // padded NHWC, permuted ch
__device__ __align__(16) float  g_wB[72 * 64 * 8];           // [kstep][o][slot8] tf32
__device__ double g_sum[C64];
__device__ double g_ssq[C64];
__device__ float  g_scale[C64];
__device__ float  g_shift[C64];

static __device__ __forceinline__ uint32_t tf32_rna(float x) {
    uint32_t u;
    asm("cvt.rna.tf32.f32 %0, %1;" : "=r"(u) : "f"(x));
    return u;
}

static __device__ __forceinline__ void mma8(float* d, const uint32_t* a,
                                            const uint32_t* b) {
    asm volatile(
        "mma.sync.aligned.m16n8k8.row.col.f32.tf32.tf32.f32 "
        "{%0,%1,%2,%3},{%4,%5,%6,%7},{%8,%9},{%0,%1,%2,%3};"
        : "+f"(d[0]), "+f"(d[1]), "+f"(d[2]), "+f"(d[3])
        : "r"(a[0]), "r"(a[1]), "r"(a[2]), "r"(a[3]), "r"(b[0]), "r"(b[1]));
}
static __device__ __forceinline__ void cp16(uint32_t dst, const void* src) {
    asm volatile("cp.async.cg.shared.global [%0], [%1], 16;"
                 :: "r"(dst), "l"(src));
}
static __device__ __forceinline__ void pair_bar(int id) {
    asm volatile("bar.sync %0, 64;" :: "r"(id) : "memory");
}
// 32-bit shared-memory LDS.64 straight into MMA operand registers
static __device__ __forceinline__ void lds64(uint32_t& a, uint32_t& b,
                                             uint32_t addr) {
    asm volatile("ld.shared.v2.b32 {%0,%1}, [%2];"
                 : "=r"(a), "=r"(b) : "r"(addr));
}

// ---------------- kernel: fold 3x3-ternary + 1x1, emit permuted tf32 -----
__global__ void fold_k(const float* __restrict__ w1x1,
                       const float* __restrict__ w_bin) {
    int t = blockIdx.x * 256 + threadIdx.x;
    if (t < C64) { g_sum[t] = 0.0; g_ssq[t] = 0.0; }
    if (t >= 64 * 9 * 64) return;
    int o = t & 63;
    int k = (t >> 6) % 9;        // tap
    int i = t / 576;             // in channel
    float s = 0.f;
    #pragma unroll 8
    for (int m = 0; m < 64; ++m)
        s += w1x1[o * 64 + m] * w_bin[(m * 64 + i) * 9 + k];
    int q8 = i >> 3, c8 = i & 7;
    int slot = (c8 & 3) * 2 + (c8 >> 2);
    g_wB[((q8 * 9 + k) * 64 + o) * 8 + slot] = __uint_as_float(tf32_rna(s));
}

// ---------------- kernel: zero padded border ----------------
__global__ void pad_zero() {
    int p = blockIdx.x;      // 0..899
    int b = blockIdx.y;
    int hp, wp;
    if (p < 226)      { hp = 0;   wp = p; }
    else if (p < 452) { hp = 225; wp = p - 226; }
    else { int q = p - 452; hp = 1 + (q >> 1); wp = (q & 1) * 225; }
    g_xpad[(((size_t)b * HP + hp) * HP + wp) * 64 + threadIdx.x] = 0.f;
}

// ---------------- kernel: NCHW -> padded NHWC, tf32-rounded, permuted ----
__global__ void pad_tr(const float* __restrict__ x) {
    __shared__ float s[64][33];
    int lx = threadIdx.x, ly = threadIdx.y;   // 32, 8
    int w0 = blockIdx.x * 32, h = blockIdx.y, b = blockIdx.z;
    #pragma unroll
    for (int i = 0; i < 8; ++i) {
        int c = i * 8 + ly;
        s[c][lx] = x[(((size_t)b * 64 + c) * HW + h) * HW + w0 + lx];
    }
    __syncthreads();
    float* dst = g_xpad + (((size_t)b * HP + h + 1) * HP + w0 + 1) * 64;
    #pragma unroll
    for (int jj = 0; jj < 8; ++jj) {
        int f = jj * 256 + ly * 32 + lx;
        int ch = f & 63, px = f >> 6;
        dst[(size_t)px * 64 + PERM64(ch)] = __uint_as_float(tf32_rna(s[ch][px]));
    }
}

// ---------------- kernel: pair-decoupled tf32 mma conv + BN stats --------
// Round-12 structure (7 independent 2-warp pair domains, triple-buffered
// cp.async distance-1, LDS.64 B layout) + incremental tile addressing +
// 32-bit immediate-offset shared loads (asm lds) to kill integer overhead.
__global__ __launch_bounds__(NTHR, 1)
void conv_mma(const float* __restrict__ bias, float* __restrict__ out) {
    extern __shared__ __align__(16) float sm[];
    const int tid = threadIdx.x;
    const int lane = tid & 31, wid = tid >> 5;
    const int wn = wid & 1, wm = wid >> 1;       // 7 m-pairs x 2 n-warps
    const int ptid = tid & 63;                    // thread-in-pair
    const int gr = lane >> 2, gc = lane & 3;
    const uint32_t smb = (uint32_t)__cvta_generic_to_shared(sm);

    // weights + bias -> SMEM once; zero reduction slots
    for (int i = tid; i < 9216; i += NTHR)
        ((float4*)(sm + SM_B))[i] = ((const float4*)g_wB)[i];
    if (tid < 64) sm[SM_BIAS + tid] = bias[tid];
    if (tid < 128) sm[SM_RED + tid] = 0.f;
    __syncthreads();    // B/bias visible; only CTA-wide bar until the end

    // hoisted per-pair-thread cp.async offsets (204 cp16 per pair-stage)
    uint32_t srcF[4], dstB[4];
    #pragma unroll
    for (int k = 0; k < 4; ++k) {
        int i = ptid + k * 64;
        if (i < 204) {
            int r = i / 68, rem = i % 68;
            int px = rem >> 1, c4 = rem & 1;
            srcF[k] = (uint32_t)((r * HP + wm * 32 + px) * 64 + c4 * 4);
            dstB[k] = smb + (uint32_t)((SM_A + wm * (3 * ABUFP)
                          + r * AROWP + px * 8 + c4 * 4) * 4);
        }
    }
    const int ncp = (ptid < 12) ? 4 : 3;

    // 32-bit fragment base addresses
    const uint32_t aBase = smb + (uint32_t)((SM_A + wm * (3 * ABUFP)
                              + gr * 8 + gc * 2) * 4);
    const uint32_t bBase = smb + (uint32_t)((SM_B + (wn * 32 + gr) * 8
                              + gc * 2) * 4);

    const int ntiles = (NTILE - blockIdx.x + NCTA - 1) / NCTA;

    auto issue = [&](const float* xrow, uint32_t boff) {
        #pragma unroll
        for (int k = 0; k < 4; ++k)
            if (k < ncp) cp16(dstB[k] + boff, xrow + srcF[k]);
        asm volatile("cp.async.commit_group;");
    };

    float ps[4][2], qs[4][2];   // per-thread BN partials
    #pragma unroll
    for (int ns = 0; ns < 4; ++ns)
        ps[ns][0] = ps[ns][1] = qs[ns][0] = qs[ns][1] = 0.f;

    // incremental tile coords (bid < 148 < 224 -> h=bid, b=0)
    int b = 0, h = blockIdx.x;
    const float* xcur = g_xpad + ((size_t)h * HP) * 64;

    issue(xcur, 0);             // stage 0, buffer 0
    int nb = 1;                 // buffer index of stage g+1 (mod 3)

    for (int j = 0; j < ntiles; ++j) {
        const bool lastj = (j == ntiles - 1);
        int hn = h + NCTA, bn = b;
        if (hn >= 224) { hn -= 224; bn += 1; }
        const float* xnxt = g_xpad + (((size_t)bn * HP + hn) * HP) * 64;

        float acc[2][4][4];
        #pragma unroll
        for (int ms = 0; ms < 2; ++ms)
            #pragma unroll
            for (int ns = 0; ns < 4; ++ns)
                #pragma unroll
                for (int q2 = 0; q2 < 4; ++q2) acc[ms][ns][q2] = 0.f;

        #pragma unroll
        for (int q8 = 0; q8 < 8; ++q8) {
            // issue stage g+1, then wait for stage g
            if (q8 < 7) {
                issue(xcur + (q8 + 1) * 8, (uint32_t)nb * ABUF4);
                asm volatile("cp.async.wait_group 1;");
            } else if (!lastj) {
                issue(xnxt, (uint32_t)nb * ABUF4);
                asm volatile("cp.async.wait_group 1;");
            } else {
                asm volatile("cp.async.wait_group 0;");
            }
            nb = (nb == 2) ? 0 : nb + 1;
            pair_bar(wm + 1);          // copy g visible to both pair warps

            // cb = buffer of stage g (== nb+1 mod 3 after increment)
            const int cb = (nb == 2) ? 0 : nb + 1;
            const uint32_t aA = aBase + (uint32_t)cb * ABUF4;
            #pragma unroll
            for (int kh = 0; kh < 3; ++kh) {
                #pragma unroll
                for (int kw = 0; kw < 3; ++kw) {
                    const uint32_t ao = aA + (uint32_t)(kh * 1152 + kw * 32);
                    uint32_t A0[4], A1[4], B0[2], B1[2], B2[2], B3[2];
                    lds64(A0[0], A0[2], ao);
                    lds64(A0[1], A0[3], ao + 256);
                    lds64(A1[0], A1[2], ao + 512);
                    lds64(A1[1], A1[3], ao + 768);
                    const uint32_t bo = bBase
                        + (uint32_t)(q8 * 18432 + (kh * 3 + kw) * 2048);
                    lds64(B0[0], B0[1], bo);
                    lds64(B1[0], B1[1], bo + 256);
                    lds64(B2[0], B2[1], bo + 512);
                    lds64(B3[0], B3[1], bo + 768);
                    mma8(acc[0][0], A0, B0);
                    mma8(acc[1][0], A1, B0);
                    mma8(acc[0][1], A0, B1);
                    mma8(acc[1][1], A1, B1);
                    mma8(acc[0][2], A0, B2);
                    mma8(acc[1][2], A1, B2);
                    mma8(acc[0][3], A0, B3);
                    mma8(acc[1][3], A1, B3);
                }
            }
        }

        // epilogue: + bias, NCHW store, BN partials
        {
            const size_t chstr = (size_t)HW * HW;
            const int pxb = wm * 32 + gr;
            const int ob  = wn * 32 + gc * 2;
            float* obase = out + ((size_t)b * 64) * chstr + (size_t)h * HW;
            #pragma unroll
            for (int ms = 0; ms < 2; ++ms) {
                #pragma unroll
                for (int ns = 0; ns < 4; ++ns) {
                    int o0 = ob + ns * 8;
                    float b0 = sm[SM_BIAS + o0], b1 = sm[SM_BIAS + o0 + 1];
                    float y0 = acc[ms][ns][0] + b0;
                    float y1 = acc[ms][ns][1] + b1;
                    float y2 = acc[ms][ns][2] + b0;
                    float y3 = acc[ms][ns][3] + b1;
                    float* p = obase + (size_t)o0 * chstr + pxb + ms * 16;
                    p[0]         = y0;
                    p[chstr]     = y1;
                    p[8]         = y2;
                    p[chstr + 8] = y3;
                    ps[ns][0] += y0 + y2;  qs[ns][0] += y0 * y0 + y2 * y2;
                    ps[ns][1] += y1 + y3;  qs[ns][1] += y1 * y1 + y3 * y3;
                }
            }
        }
        b = bn; h = hn; xcur = xnxt;
    }

    // BN partial reduction: regs -> shared -> global doubles
    #pragma unroll
    for (int ns = 0; ns < 4; ++ns) {
        int o0 = wn * 32 + ns * 8 + gc * 2;
        atomicAdd(&sm[SM_RED + o0],          ps[ns][0]);
        atomicAdd(&sm[SM_RED + o0 + 1],      ps[ns][1]);
        atomicAdd(&sm[SM_RED + 64 + o0],     qs[ns][0]);
        atomicAdd(&sm[SM_RED + 64 + o0 + 1], qs[ns][1]);
    }
    __syncthreads();
    if (tid < 64) {
        atomicAdd(&g_sum[tid], (double)sm[SM_RED + tid]);
        atomicAdd(&g_ssq[tid], (double)sm[SM_RED + 64 + tid]);
    }
}

// ---------------- kernel: finalize BN ----------------
__global__ void stats_k(const float* __restrict__ gamma,
                        const float* __restrict__ beta) {
    int c = threadIdx.x;
    if (c >= C64) return;
    double m = g_sum[c] / (double)NPIX;
    double v = g_ssq[c] / (double)NPIX - m * m;
    float a = gamma[c] * rsqrtf((float)v + EPS_BN);
    g_scale[c] = a;
    g_shift[c] = beta[c] - (float)m * a;
}

// ---------------- kernel: normalize + leaky relu + clamp ----------------
__global__ void act_k(float* __restrict__ out) {
    int idx = blockIdx.x * blockDim.x + threadIdx.x;
    const int total4 = NB * C64 * HW * HW / 4;
    if (idx >= total4) return;
    int plane = (idx * 4) / (HW * HW);
    int c = plane & 63;
    float a = g_scale[c], sh = g_shift[c];
    float4 v = ((float4*)out)[idx];
    float* vp = &v.x;
    #pragma unroll
    for (int p = 0; p < 4; ++p) {
        float y = a * vp[p] + sh;
        y = (y >= 0.f) ? y : LEAK * y;
        y = fminf(fmaxf(y, 0.f), CEILV);
        vp[p] = y;
    }
    ((float4*)out)[idx] = v;
}

// ---------------- launch ----------------
extern "C" void kernel_launch(void* const* d_in, const int* in_sizes, int n_in,
                              void* d_out, int out_size) {
    const float* x     = (const float*)d_in[0];
    const float* w_bin = (const float*)d_in[1];
    const float* w1x1  = (const float*)d_in[2];
    const float* b1x1  = (const float*)d_in[3];
    const float* gamma = (const float*)d_in[4];
    const float* beta  = (const float*)d_in[5];
    float* out = (float*)d_out;

    cudaFuncSetAttribute(conv_mma, cudaFuncAttributeMaxDynamicSharedMemorySize,
                         SMEM_DYN);

    fold_k<<<(64 * 9 * 64 + 255) / 256, 256>>>(w1x1, w_bin);
    pad_zero<<<dim3(900, NB), 64>>>();
    pad_tr<<<dim3(7, HW, NB), dim3(32, 8)>>>(x);
    conv_mma<<<NCTA, NTHR, SMEM_DYN>>>(b1x1, out);
    stats_k<<<1, 64>>>(gamma, beta);
    int total4 = NB * C64 * HW * HW / 4;
    act_k<<<(total4 + 255) / 256, 256>>>(out);
}

// round 16
// speedup vs baseline: 1.0312x; 1.0033x over previous
#include <cuda_runtime.h>
#include <cstdint>

#define C64    64
#define HW     224
#define HP     226
#define NB     8
#define NPIX   (NB * HW * HW)
#define EPS_BN 1e-5f
#define LEAK   0.1f
#define CEILV  255.0f

#define NTILE  1792            /* 8 b * 224 rows; tile = full row, 224px x 64oc */
#define NCTA   148
#define NTHR   448             /* 14 warps: 7 m-pairs x 2 n */

// SMEM float-index layout
#define SM_BIAS 0              /* 64 floats */
#define SM_RED  64             /* 128 floats: sum[64], ssq[64] */
#define SM_B    192            /* 72*64*8 = 36864 floats, [kstep][o][slot8] */
#define SM_A    37056          /* 7 pairs x 3 bufs x 864 floats */
#define ABUFP   864            /* per pair-buffer: 3 rows * 36 px * 8 ch */
#define ABUF4   3456           /* bytes per pair-buffer */
#define AROWP   288            /* 36 px * 8 floats */
#define SM_FLTS (37056 + 7 * 3 * ABUFP)
#define SMEM_DYN (SM_FLTS * 4) /* 220800 B */

// permutation within each 8-channel group: slot = (c&3)*2 + (c>>2)
#define PERM64(c) (((c) & ~7) | (((c) & 3) << 1) | (((c) >> 2) & 1))

// ---------------- device scratch ----------------
__device__ __align__(16) float  g_xpad[NB * HP * HP * C64];  // padded NHWC, permuted ch
__device__ __align__(16) float  g_wB[72 * 64 * 8];           // [kstep][o][slot8] tf32
__device__ double g_sum[C64];
__device__ double g_ssq[C64];
__device__ float  g_scale[C64];
__device__ float  g_shift[C64];

static __device__ __forceinline__ uint32_t tf32_rna(float x) {
    uint32_t u;
    asm("cvt.rna.tf32.f32 %0, %1;" : "=r"(u) : "f"(x));
    return u;
}

static __device__ __forceinline__ void mma8(float* d, const uint32_t* a,
                                            const uint32_t* b) {
    asm volatile(
        "mma.sync.aligned.m16n8k8.row.col.f32.tf32.tf32.f32 "
        "{%0,%1,%2,%3},{%4,%5,%6,%7},{%8,%9},{%0,%1,%2,%3};"
        : "+f"(d[0]), "+f"(d[1]), "+f"(d[2]), "+f"(d[3])
        : "r"(a[0]), "r"(a[1]), "r"(a[2]), "r"(a[3]), "r"(b[0]), "r"(b[1]));
}
static __device__ __forceinline__ void cp16(uint32_t dst, const void* src) {
    asm volatile("cp.async.cg.shared.global [%0], [%1], 16;"
                 :: "r"(dst), "l"(src));
}
static __device__ __forceinline__ void pair_bar(int id) {
    asm volatile("bar.sync %0, 64;" :: "r"(id) : "memory");
}
// 32-bit shared-memory LDS.64 straight into MMA operand registers
static __device__ __forceinline__ void lds64(uint32_t& a, uint32_t& b,
                                             uint32_t addr) {
    asm volatile("ld.shared.v2.b32 {%0,%1}, [%2];"
                 : "=r"(a), "=r"(b) : "r"(addr));
}

// ---------------- kernel: fold 3x3-ternary + 1x1, emit permuted tf32 -----
__global__ void fold_k(const float* __restrict__ w1x1,
                       const float* __restrict__ w_bin) {
    int t = blockIdx.x * 256 + threadIdx.x;
    if (t < C64) { g_sum[t] = 0.0; g_ssq[t] = 0.0; }
    if (t >= 64 * 9 * 64) return;
    int o = t & 63;
    int k = (t >> 6) % 9;        // tap
    int i = t / 576;             // in channel
    float s = 0.f;
    #pragma unroll 8
    for (int m = 0; m < 64; ++m)
        s += w1x1[o * 64 + m] * w_bin[(m * 64 + i) * 9 + k];
    int q8 = i >> 3, c8 = i & 7;
    int slot = (c8 & 3) * 2 + (c8 >> 2);
    g_wB[((q8 * 9 + k) * 64 + o) * 8 + slot] = __uint_as_float(tf32_rna(s));
}

// ---------------- kernel: zero padded border ----------------
__global__ void pad_zero() {
    int p = blockIdx.x;      // 0..899
    int b = blockIdx.y;
    int hp, wp;
    if (p < 226)      { hp = 0;   wp = p; }
    else if (p < 452) { hp = 225; wp = p - 226; }
    else { int q = p - 452; hp = 1 + (q >> 1); wp = (q & 1) * 225; }
    g_xpad[(((size_t)b * HP + hp) * HP + wp) * 64 + threadIdx.x] = 0.f;
}

// ---------------- kernel: NCHW -> padded NHWC, tf32-rounded, permuted ----
__global__ void pad_tr(const float* __restrict__ x) {
    __shared__ float s[64][33];
    int lx = threadIdx.x, ly = threadIdx.y;   // 32, 8
    int w0 = blockIdx.x * 32, h = blockIdx.y, b = blockIdx.z;
    #pragma unroll
    for (int i = 0; i < 8; ++i) {
        int c = i * 8 + ly;
        s[c][lx] = x[(((size_t)b * 64 + c) * HW + h) * HW + w0 + lx];
    }
    __syncthreads();
    float* dst = g_xpad + (((size_t)b * HP + h + 1) * HP + w0 + 1) * 64;
    #pragma unroll
    for (int jj = 0; jj < 8; ++jj) {
        int f = jj * 256 + ly * 32 + lx;
        int ch = f & 63, px = f >> 6;
        dst[(size_t)px * 64 + PERM64(ch)] = __uint_as_float(tf32_rna(s[ch][px]));
    }
}

// ---------------- kernel: pair-decoupled tf32 mma conv + BN stats --------
// Round-15 base (pair domains, 32-bit LDS, incremental addressing)
// + distance-2 cp.async prefetch (all 3 buffers) + B-fragment lookahead
// (tap t+1 B loads issued before tap t MMAs; stage tap-0 B loads issued
// before pair_bar, overlapping the barrier/copy wait).
__global__ __launch_bounds__(NTHR, 1)
void conv_mma(const float* __restrict__ bias, float* __restrict__ out) {
    extern __shared__ __align__(16) float sm[];
    const int tid = threadIdx.x;
    const int lane = tid & 31, wid = tid >> 5;
    const int wn = wid & 1, wm = wid >> 1;       // 7 m-pairs x 2 n-warps
    const int ptid = tid & 63;                    // thread-in-pair
    const int gr = lane >> 2, gc = lane & 3;
    const uint32_t smb = (uint32_t)__cvta_generic_to_shared(sm);

    // weights + bias -> SMEM once; zero reduction slots
    for (int i = tid; i < 9216; i += NTHR)
        ((float4*)(sm + SM_B))[i] = ((const float4*)g_wB)[i];
    if (tid < 64) sm[SM_BIAS + tid] = bias[tid];
    if (tid < 128) sm[SM_RED + tid] = 0.f;
    __syncthreads();    // B/bias visible; only CTA-wide bar until the end

    // hoisted per-pair-thread cp.async offsets (204 cp16 per pair-stage)
    uint32_t srcF[4], dstB[4];
    #pragma unroll
    for (int k = 0; k < 4; ++k) {
        int i = ptid + k * 64;
        if (i < 204) {
            int r = i / 68, rem = i % 68;
            int px = rem >> 1, c4 = rem & 1;
            srcF[k] = (uint32_t)((r * HP + wm * 32 + px) * 64 + c4 * 4);
            dstB[k] = smb + (uint32_t)((SM_A + wm * (3 * ABUFP)
                          + r * AROWP + px * 8 + c4 * 4) * 4);
        }
    }
    const int ncp = (ptid < 12) ? 4 : 3;

    // 32-bit fragment base addresses
    const uint32_t aBase = smb + (uint32_t)((SM_A + wm * (3 * ABUFP)
                              + gr * 8 + gc * 2) * 4);
    const uint32_t bBase = smb + (uint32_t)((SM_B + (wn * 32 + gr) * 8
                              + gc * 2) * 4);

    const int ntiles = (NTILE - blockIdx.x + NCTA - 1) / NCTA;
    const int nstage = ntiles * 8;

    auto issue = [&](const float* xrow, uint32_t boff) {
        #pragma unroll
        for (int k = 0; k < 4; ++k)
            if (k < ncp) cp16(dstB[k] + boff, xrow + srcF[k]);
        asm volatile("cp.async.commit_group;");
    };

    float ps[4][2], qs[4][2];   // per-thread BN partials
    #pragma unroll
    for (int ns = 0; ns < 4; ++ns)
        ps[ns][0] = ps[ns][1] = qs[ns][0] = qs[ns][1] = 0.f;

    // incremental tile coords (bid < 148 < 224 -> h=bid, b=0)
    int b = 0, h = blockIdx.x;
    const float* xcur = g_xpad + ((size_t)h * HP) * 64;

    issue(xcur, 0);                         // stage 0 -> buf 0
    if (nstage > 1) issue(xcur + 8, ABUF4); // stage 1 -> buf 1
    int nb = 2;     // buffer for next issue (stage 2)
    int cbuf = 0;   // buffer of current compute stage

    for (int j = 0; j < ntiles; ++j) {
        const bool lastj = (j == ntiles - 1);
        int hn = h + NCTA, bn = b;
        if (hn >= 224) { hn -= 224; bn += 1; }
        const float* xnxt = g_xpad + (((size_t)bn * HP + hn) * HP) * 64;

        float acc[2][4][4];
        #pragma unroll
        for (int ms = 0; ms < 2; ++ms)
            #pragma unroll
            for (int ns = 0; ns < 4; ++ns)
                #pragma unroll
                for (int q2 = 0; q2 < 4; ++q2) acc[ms][ns][q2] = 0.f;

        #pragma unroll
        for (int q8 = 0; q8 < 8; ++q8) {
            // wait for stage g (two stages in flight; final stage waits all)
            if (q8 == 7 && lastj) asm volatile("cp.async.wait_group 0;");
            else                  asm volatile("cp.async.wait_group 1;");

            // preload B frags for tap 0 (static SMEM, no sync needed)
            const uint32_t bq = bBase + (uint32_t)(q8 * 18432);
            uint32_t Bf[2][4][2];
            lds64(Bf[0][0][0], Bf[0][0][1], bq);
            lds64(Bf[0][1][0], Bf[0][1][1], bq + 256);
            lds64(Bf[0][2][0], Bf[0][2][1], bq + 512);
            lds64(Bf[0][3][0], Bf[0][3][1], bq + 768);

            pair_bar(wm + 1);          // copy g visible to both pair warps

            // issue stage g+2 (buffer (g+2)%3 == (g-1)%3: partner done
            // reading it -- it passed pair_bar(g) above)
            {
                int gi = j * 8 + q8 + 2;
                if (gi < nstage) {
                    const float* xb = ((gi >> 3) == j)
                        ? (xcur + (gi & 7) * 8) : (xnxt + (gi & 7) * 8);
                    issue(xb, (uint32_t)nb * ABUF4);
                    nb = (nb == 2) ? 0 : nb + 1;
                }
            }

            const uint32_t aA = aBase + (uint32_t)cbuf * ABUF4;
            cbuf = (cbuf == 2) ? 0 : cbuf + 1;

            #pragma unroll
            for (int t = 0; t < 9; ++t) {
                const int kh = t / 3, kw = t % 3;
                const uint32_t ao = aA + (uint32_t)(kh * 1152 + kw * 32);
                uint32_t A0[4], A1[4];
                lds64(A0[0], A0[2], ao);
                lds64(A0[1], A0[3], ao + 256);
                lds64(A1[0], A1[2], ao + 512);
                lds64(A1[1], A1[3], ao + 768);
                const int cur = t & 1, nxt = cur ^ 1;
                if (t < 8) {            // lookahead: B frags for tap t+1
                    const uint32_t bo = bq + (uint32_t)((t + 1) * 2048);
                    lds64(Bf[nxt][0][0], Bf[nxt][0][1], bo);
                    lds64(Bf[nxt][1][0], Bf[nxt][1][1], bo + 256);
                    lds64(Bf[nxt][2][0], Bf[nxt][2][1], bo + 512);
                    lds64(Bf[nxt][3][0], Bf[nxt][3][1], bo + 768);
                }
                mma8(acc[0][0], A0, Bf[cur][0]);
                mma8(acc[1][0], A1, Bf[cur][0]);
                mma8(acc[0][1], A0, Bf[cur][1]);
                mma8(acc[1][1], A1, Bf[cur][1]);
                mma8(acc[0][2], A0, Bf[cur][2]);
                mma8(acc[1][2], A1, Bf[cur][2]);
                mma8(acc[0][3], A0, Bf[cur][3]);
                mma8(acc[1][3], A1, Bf[cur][3]);
            }
        }

        // epilogue: + bias, NCHW store, BN partials
        {
            const size_t chstr = (size_t)HW * HW;
            const int pxb = wm * 32 + gr;
            const int ob  = wn * 32 + gc * 2;
            float* obase = out + ((size_t)b * 64) * chstr + (size_t)h * HW;
            #pragma unroll
            for (int ms = 0; ms < 2; ++ms) {
                #pragma unroll
                for (int ns = 0; ns < 4; ++ns) {
                    int o0 = ob + ns * 8;
                    float b0 = sm[SM_BIAS + o0], b1 = sm[SM_BIAS + o0 + 1];
                    float y0 = acc[ms][ns][0] + b0;
                    float y1 = acc[ms][ns][1] + b1;
                    float y2 = acc[ms][ns][2] + b0;
                    float y3 = acc[ms][ns][3] + b1;
                    float* p = obase + (size_t)o0 * chstr + pxb + ms * 16;
                    p[0]         = y0;
                    p[chstr]     = y1;
                    p[8]         = y2;
                    p[chstr + 8] = y3;
                    ps[ns][0] += y0 + y2;  qs[ns][0] += y0 * y0 + y2 * y2;
                    ps[ns][1] += y1 + y3;  qs[ns][1] += y1 * y1 + y3 * y3;
                }
            }
        }
        b = bn; h = hn; xcur = xnxt;
    }

    // BN partial reduction: regs -> shared -> global doubles
    #pragma unroll
    for (int ns = 0; ns < 4; ++ns) {
        int o0 = wn * 32 + ns * 8 + gc * 2;
        atomicAdd(&sm[SM_RED + o0],          ps[ns][0]);
        atomicAdd(&sm[SM_RED + o0 + 1],      ps[ns][1]);
        atomicAdd(&sm[SM_RED + 64 + o0],     qs[ns][0]);
        atomicAdd(&sm[SM_RED + 64 + o0 + 1], qs[ns][1]);
    }
    __syncthreads();
    if (tid < 64) {
        atomicAdd(&g_sum[tid], (double)sm[SM_RED + tid]);
        atomicAdd(&g_ssq[tid], (double)sm[SM_RED + 64 + tid]);
    }
}

// ---------------- kernel: finalize BN ----------------
__global__ void stats_k(const float* __restrict__ gamma,
                        const float* __restrict__ beta) {
    int c = threadIdx.x;
    if (c >= C64) return;
    double m = g_sum[c] / (double)NPIX;
    double v = g_ssq[c] / (double)NPIX - m * m;
    float a = gamma[c] * rsqrtf((float)v + EPS_BN);
    g_scale[c] = a;
    g_shift[c] = beta[c] - (float)m * a;
}

// ---------------- kernel: normalize + leaky relu + clamp ----------------
__global__ void act_k(float* __restrict__ out) {
    int idx = blockIdx.x * blockDim.x + threadIdx.x;
    const int total4 = NB * C64 * HW * HW / 4;
    if (idx >= total4) return;
    int plane = (idx * 4) / (HW * HW);
    int c = plane & 63;
    float a = g_scale[c], sh = g_shift[c];
    float4 v = ((float4*)out)[idx];
    float* vp = &v.x;
    #pragma unroll
    for (int p = 0; p < 4; ++p) {
        float y = a * vp[p] + sh;
        y = (y >= 0.f) ? y : LEAK * y;
        y = fminf(fmaxf(y, 0.f), CEILV);
        vp[p] = y;
    }
    ((float4*)out)[idx] = v;
}

// ---------------- launch ----------------
extern "C" void kernel_launch(void* const* d_in, const int* in_sizes, int n_in,
                              void* d_out, int out_size) {
    const float* x     = (const float*)d_in[0];
    const float* w_bin = (const float*)d_in[1];
    const float* w1x1  = (const float*)d_in[2];
    const float* b1x1  = (const float*)d_in[3];
    const float* gamma = (const float*)d_in[4];
    const float* beta  = (const float*)d_in[5];
    float* out = (float*)d_out;

    cudaFuncSetAttribute(conv_mma, cudaFuncAttributeMaxDynamicSharedMemorySize,
                         SMEM_DYN);

    fold_k<<<(64 * 9 * 64 + 255) / 256, 256>>>(w1x1, w_bin);
    pad_zero<<<dim3(900, NB), 64>>>();
    pad_tr<<<dim3(7, HW, NB), dim3(32, 8)>>>(x);
    conv_mma<<<NCTA, NTHR, SMEM_DYN>>>(b1x1, out);
    stats_k<<<1, 64>>>(gamma, beta);
    int total4 = NB * C64 * HW * HW / 4;
    act_k<<<(total4 + 255) / 256, 256>>>(out);
}